// round 13
// baseline (speedup 1.0000x reference)
#include <cuda_runtime.h>
#include <cuda_fp16.h>
#include <cstdint>
#include <math.h>

// Problem dims
#define Bn   16384
#define Tn   3
#define Dn   512
#define Gn   4
#define NEn  4
#define NEXP 16
#define Hn   512
#define En   256
#define GHn  256
#define THn  128
#define TOn  64

// ---------------- scratch (device globals; no allocs allowed) ----------------
__device__ __half s_in  [(size_t)Bn * Gn * Dn];
__device__ __half s_gin [(size_t)Bn * Tn * Dn];
__device__ __half s_h1  [(size_t)Bn * NEXP * Hn];
__device__ __half s_we1 [(size_t)NEXP * Dn * Hn];
__device__ __half s_we2 [(size_t)NEXP * Hn * En];
__device__ __half s_wg1 [(size_t)Tn * Dn * GHn];
__device__ __half s_wt1 [(size_t)Tn * En * THn];
__device__ __half s_aggh[(size_t)Bn * Tn * En];
__device__ float g_emb[(size_t)Bn * NEXP * En];
__device__ float g_gh [(size_t)Bn * Tn * GHn];
__device__ float g_gw [(size_t)Bn * Tn * NEXP];
__device__ float g_th [(size_t)Bn * Tn * THn];

// ---------------- helpers ----------------
__device__ __forceinline__ uint2 pack_h4(float4 v) {
    uint2 r;
    r.x = (unsigned)__half_as_ushort(__float2half_rn(v.x))
        | ((unsigned)__half_as_ushort(__float2half_rn(v.y)) << 16);
    r.y = (unsigned)__half_as_ushort(__float2half_rn(v.z))
        | ((unsigned)__half_as_ushort(__float2half_rn(v.w)) << 16);
    return r;
}

// ---------------- fused conversion kernel (all fp32->fp16 staging) ----------
#define N_IN  ((long)Bn * Gn * Dn / 4)
#define N_GIN ((long)Bn * Tn * Dn / 4)
#define N_E1  ((long)NEXP * Dn * Hn / 4)
#define N_E2  ((long)NEXP * Hn * En / 4)
#define N_G1  ((long)Tn * Dn * GHn / 4)
#define N_T1  ((long)Tn * En * THn / 4)
#define N_ALL (N_IN + N_GIN + N_E1 + N_E2 + N_G1 + N_T1)

__global__ void conv_all(const float* __restrict__ in,
                         const float* __restrict__ eW1, const float* __restrict__ eW2,
                         const float* __restrict__ gW1, const float* __restrict__ tW1) {
    long i = (long)blockIdx.x * blockDim.x + threadIdx.x;
    if (i < N_IN) {
        ((uint2*)s_in)[i] = pack_h4(((const float4*)in)[i]);
        return;
    }
    i -= N_IN;
    if (i < N_GIN) {
        int d4 = (int)(i % (Dn / 4));
        long bt = i / (Dn / 4);
        int t  = (int)(bt % Tn);
        long b = bt / Tn;
        const float4* base = (const float4*)(in + b * Gn * Dn);
        float4 a = base[(long)(t + 1) * (Dn / 4) + d4];
        float4 s = base[d4];
        ((uint2*)s_gin)[i] = pack_h4(make_float4(a.x + s.x, a.y + s.y, a.z + s.z, a.w + s.w));
        return;
    }
    i -= N_GIN;
    if (i < N_E1) { ((uint2*)s_we1)[i] = pack_h4(((const float4*)eW1)[i]); return; }
    i -= N_E1;
    if (i < N_E2) { ((uint2*)s_we2)[i] = pack_h4(((const float4*)eW2)[i]); return; }
    i -= N_E2;
    if (i < N_G1) { ((uint2*)s_wg1)[i] = pack_h4(((const float4*)gW1)[i]); return; }
    i -= N_G1;
    if (i < N_T1) { ((uint2*)s_wt1)[i] = pack_h4(((const float4*)tW1)[i]); }
}

// ===========================================================================
// Tensor-core batched GEMM: single fp16 A and B.
// 4-slot smem ring, register prefetch distance 2, barrier every 2 iters.
// A [M,K] row-major; B [K,N] row-major. C = A@B + bias [+relu].
// Block tile 128x128x32, 256 threads (8 warps: 2M x 4N), warp tile 64x32.
// 2 CTAs/SM (smem 75.8KB/CTA).
// ===========================================================================
#define APITCH 40
#define BPITCH 136
#define A_OFF  0
#define B_OFF (128 * APITCH)                         // 5120
#define BUF_ELEMS (128 * APITCH + 32 * BPITCH)       // 9472
#define STG_B (BUF_ELEMS * 2)                        // 18944 bytes/slot
#define TC_SMEM (4 * STG_B)                          // 75776 bytes

__device__ __forceinline__ void mma_f16(float* c, const unsigned* a, const unsigned* b) {
    asm volatile(
        "mma.sync.aligned.m16n8k16.row.col.f32.f16.f16.f32 "
        "{%0,%1,%2,%3},{%4,%5,%6,%7},{%8,%9},{%0,%1,%2,%3};"
        : "+f"(c[0]), "+f"(c[1]), "+f"(c[2]), "+f"(c[3])
        : "r"(a[0]), "r"(a[1]), "r"(a[2]), "r"(a[3]), "r"(b[0]), "r"(b[1]));
}
__device__ __forceinline__ void ldsm4(unsigned& r0, unsigned& r1,
                                      unsigned& r2, unsigned& r3, unsigned addr) {
    asm volatile("ldmatrix.sync.aligned.m8n8.x4.shared.b16 {%0,%1,%2,%3},[%4];"
                 : "=r"(r0), "=r"(r1), "=r"(r2), "=r"(r3) : "r"(addr));
}
__device__ __forceinline__ void ldsm4t(unsigned& r0, unsigned& r1,
                                       unsigned& r2, unsigned& r3, unsigned addr) {
    asm volatile("ldmatrix.sync.aligned.m8n8.x4.trans.shared.b16 {%0,%1,%2,%3},[%4];"
                 : "=r"(r0), "=r"(r1), "=r"(r2), "=r"(r3) : "r"(addr));
}

__global__ void __launch_bounds__(256, 2)
tc_gemm(const __half* __restrict__ A, const __half* __restrict__ Bw,
        const float* __restrict__ bias,
        float* __restrict__ C, __half* __restrict__ Chalf,
        int K, int lda, int ldb, int ldc,
        long aStride, int aDiv, long bStride, long biasStride, long cStride,
        int relu, int halfOut)
{
    extern __shared__ __half sm[];
    int z = blockIdx.z;
    A  += (long)(z / aDiv) * aStride;
    Bw += (long)z * bStride;
    bias += (long)z * biasStride;
    if (halfOut) Chalf += (long)z * cStride;
    else         C     += (long)z * cStride;

    int tid  = threadIdx.x;
    int lane = tid & 31, warp = tid >> 5;
    int row0 = blockIdx.x * 128, col0 = blockIdx.y * 128;
    int wm = (warp >> 2) * 64, wn = (warp & 3) * 32;
    int g = lane >> 2, qt = lane & 3;

    unsigned sbase = (unsigned)__cvta_generic_to_shared(sm);

    // ldmatrix per-lane offsets
    int rA = (lane & 7) + ((lane >> 3) & 1) * 8;
    int cA = ((lane >> 4) & 1) * 8;
    int rB = (lane & 7) + ((lane >> 3) & 1) * 8;
    int cB = ((lane >> 4) & 1) * 8;

    // gmem load mapping
    int aRow = tid >> 2;            // 0..63 (+64)
    int aK8  = (tid & 3) * 8;
    int bK   = tid >> 3;            // 0..31
    int bN16 = (tid & 7) * 16;

    float acc[4][4][4];
    #pragma unroll
    for (int i = 0; i < 4; i++)
        #pragma unroll
        for (int j = 0; j < 4; j++)
            #pragma unroll
            for (int k = 0; k < 4; k++) acc[i][j][k] = 0.0f;

    const __half* aSrc0 = A + (long)(row0 + aRow) * lda + aK8;
    const __half* aSrc1 = A + (long)(row0 + aRow + 64) * lda + aK8;
    const __half* bSrc  = Bw + (long)bK * ldb + col0 + bN16;

    // smem store offsets (within a slot, in halves)
    int sA0 = A_OFF + aRow * APITCH + aK8;
    int sA1 = A_OFF + (aRow + 64) * APITCH + aK8;
    int sB0 = B_OFF + bK * BPITCH + bN16;

    uint4 va0, va1, vb0, vb1;
    int nIter = K / 32;

    // prologue: fill slots 0 and 1 (tiles 0,1)
    #pragma unroll
    for (int s = 0; s < 2; s++) {
        long k0 = (long)s * 32;
        va0 = *(const uint4*)(aSrc0 + k0);
        va1 = *(const uint4*)(aSrc1 + k0);
        vb0 = *(const uint4*)(bSrc + k0 * ldb);
        vb1 = *(const uint4*)(bSrc + k0 * ldb + 8);
        __half* bp = sm + s * BUF_ELEMS;
        *(uint4*)(bp + sA0)     = va0;
        *(uint4*)(bp + sA1)     = va1;
        *(uint4*)(bp + sB0)     = vb0;
        *(uint4*)(bp + sB0 + 8) = vb1;
    }
    __syncthreads();

    for (int it = 0; it < nIter; it++) {
        bool doPre = (it + 2 < nIter);
        if (doPre) {
            long k0 = (long)(it + 2) * 32;
            va0 = *(const uint4*)(aSrc0 + k0);
            va1 = *(const uint4*)(aSrc1 + k0);
            vb0 = *(const uint4*)(bSrc + k0 * ldb);
            vb1 = *(const uint4*)(bSrc + k0 * ldb + 8);
        }

        unsigned bufb = sbase + (unsigned)(it & 3) * STG_B;

        #pragma unroll
        for (int ks = 0; ks < 32; ks += 16) {
            unsigned Af[4][4], Bf[4][2];
            #pragma unroll
            for (int mt = 0; mt < 4; mt++) {
                unsigned ad = bufb + (A_OFF + (wm + mt * 16 + rA) * APITCH + ks + cA) * 2;
                ldsm4(Af[mt][0], Af[mt][1], Af[mt][2], Af[mt][3], ad);
            }
            #pragma unroll
            for (int np = 0; np < 2; np++) {
                unsigned bd = bufb + (B_OFF + (ks + rB) * BPITCH + wn + np * 16 + cB) * 2;
                ldsm4t(Bf[2*np][0], Bf[2*np][1], Bf[2*np+1][0], Bf[2*np+1][1], bd);
            }
            #pragma unroll
            for (int mt = 0; mt < 4; mt++)
                #pragma unroll
                for (int nt = 0; nt < 4; nt++)
                    mma_f16(acc[mt][nt], Af[mt], Bf[nt]);
        }

        if (doPre) {
            __half* bp = sm + ((it + 2) & 3) * BUF_ELEMS;
            *(uint4*)(bp + sA0)     = va0;
            *(uint4*)(bp + sA1)     = va1;
            *(uint4*)(bp + sB0)     = vb0;
            *(uint4*)(bp + sB0 + 8) = vb1;
        }
        if ((it & 1) && it + 1 < nIter) __syncthreads();
    }

    // epilogue
    #pragma unroll
    for (int mt = 0; mt < 4; mt++) {
        #pragma unroll
        for (int nt = 0; nt < 4; nt++) {
            int col = col0 + wn + nt * 8 + 2 * qt;
            long r0 = row0 + wm + mt * 16 + g;
            float b0v = bias[col], b1v = bias[col + 1];
            float2 v0 = make_float2(acc[mt][nt][0] + b0v, acc[mt][nt][1] + b1v);
            float2 v1 = make_float2(acc[mt][nt][2] + b0v, acc[mt][nt][3] + b1v);
            if (relu) {
                v0.x = fmaxf(v0.x, 0.f); v0.y = fmaxf(v0.y, 0.f);
                v1.x = fmaxf(v1.x, 0.f); v1.y = fmaxf(v1.y, 0.f);
            }
            if (halfOut) {
                *(unsigned*)(Chalf + r0 * ldc + col) =
                    (unsigned)__half_as_ushort(__float2half_rn(v0.x))
                  | ((unsigned)__half_as_ushort(__float2half_rn(v0.y)) << 16);
                *(unsigned*)(Chalf + (r0 + 8) * ldc + col) =
                    (unsigned)__half_as_ushort(__float2half_rn(v1.x))
                  | ((unsigned)__half_as_ushort(__float2half_rn(v1.y)) << 16);
            } else {
                *(float2*)&C[r0 * ldc + col] = v0;
                *(float2*)&C[(r0 + 8) * ldc + col] = v1;
            }
        }
    }
}

// ---------------------------------------------------------------------------
// Scalar FFMA SGEMM for tower layer 2 (N=64).
// ---------------------------------------------------------------------------
#define BM 128
#define BN 128
#define BK 8
#define TM 8
#define TN 8

__global__ __launch_bounds__(256)
void sgemm_bias(const float* __restrict__ A, const float* __restrict__ Bw,
                const float* __restrict__ bias, float* __restrict__ C,
                int N, int K, int lda, int ldb, int ldc,
                long aStride, int aDiv, long bStride, long biasStride, long cStride,
                int relu)
{
    int z = blockIdx.z;
    A    += (long)(z / aDiv) * aStride;
    Bw   += (long)z * bStride;
    bias += (long)z * biasStride;
    C    += (long)z * cStride;

    __shared__ float As[BK][BM];
    __shared__ float Bs[BK][BN];

    int tid  = threadIdx.x;
    int row0 = blockIdx.x * BM;
    int col0 = blockIdx.y * BN;
    int tx = tid % 16;
    int ty = tid / 16;

    int aRow = tid >> 1;
    int aCol = (tid & 1) * 4;
    int bRow = tid >> 5;
    int bCol = (tid & 31) * 4;
    bool bOk = (col0 + bCol) < N;

    float acc[TM][TN];
    #pragma unroll
    for (int i = 0; i < TM; i++)
        #pragma unroll
        for (int j = 0; j < TN; j++) acc[i][j] = 0.0f;

    for (int k0 = 0; k0 < K; k0 += BK) {
        float4 av = *(const float4*)&A[(long)(row0 + aRow) * lda + k0 + aCol];
        As[aCol + 0][aRow] = av.x;
        As[aCol + 1][aRow] = av.y;
        As[aCol + 2][aRow] = av.z;
        As[aCol + 3][aRow] = av.w;
        if (bOk) {
            float4 bv = *(const float4*)&Bw[(long)(k0 + bRow) * ldb + col0 + bCol];
            *(float4*)&Bs[bRow][bCol] = bv;
        }
        __syncthreads();

        #pragma unroll
        for (int kk = 0; kk < BK; kk++) {
            float4 a0 = *(const float4*)&As[kk][ty * TM];
            float4 a1 = *(const float4*)&As[kk][ty * TM + 4];
            float4 b0 = *(const float4*)&Bs[kk][tx * TN];
            float4 b1 = *(const float4*)&Bs[kk][tx * TN + 4];
            float ra[TM] = {a0.x, a0.y, a0.z, a0.w, a1.x, a1.y, a1.z, a1.w};
            float rbv[TN] = {b0.x, b0.y, b0.z, b0.w, b1.x, b1.y, b1.z, b1.w};
            #pragma unroll
            for (int i = 0; i < TM; i++)
                #pragma unroll
                for (int j = 0; j < TN; j++)
                    acc[i][j] += ra[i] * rbv[j];
        }
        __syncthreads();
    }

    #pragma unroll
    for (int i = 0; i < TM; i++) {
        long rr = row0 + ty * TM + i;
        #pragma unroll
        for (int j0 = 0; j0 < TN; j0 += 4) {
            int c = col0 + tx * TN + j0;
            if (c < N) {
                float4 v;
                v.x = acc[i][j0 + 0] + bias[c + 0];
                v.y = acc[i][j0 + 1] + bias[c + 1];
                v.z = acc[i][j0 + 2] + bias[c + 2];
                v.w = acc[i][j0 + 3] + bias[c + 3];
                if (relu) {
                    v.x = fmaxf(v.x, 0.f); v.y = fmaxf(v.y, 0.f);
                    v.z = fmaxf(v.z, 0.f); v.w = fmaxf(v.w, 0.f);
                }
                *(float4*)&C[rr * ldc + c] = v;
            }
        }
    }
}

// ---------------------------------------------------------------------------
__global__ void gate2_softmax_kernel(const float* __restrict__ W2,
                                     const float* __restrict__ b2) {
    int t = blockIdx.y;
    __shared__ float sW[GHn * NEXP];
    __shared__ float sb[NEXP];
    for (int i = threadIdx.x; i < GHn * NEXP; i += blockDim.x)
        sW[i] = W2[(size_t)t * GHn * NEXP + i];
    if (threadIdx.x < NEXP) sb[threadIdx.x] = b2[t * NEXP + threadIdx.x];
    __syncthreads();

    int b = blockIdx.x * blockDim.x + threadIdx.x;
    if (b >= Bn) return;

    const float4* gr = (const float4*)(g_gh + ((size_t)b * Tn + t) * GHn);
    float acc[NEXP];
    #pragma unroll
    for (int k = 0; k < NEXP; k++) acc[k] = sb[k];
    for (int h4 = 0; h4 < GHn / 4; h4++) {
        float4 x = gr[h4];
        const float* w = sW + h4 * 4 * NEXP;
        #pragma unroll
        for (int k = 0; k < NEXP; k++)
            acc[k] += x.x * w[k] + x.y * w[NEXP + k]
                    + x.z * w[2 * NEXP + k] + x.w * w[3 * NEXP + k];
    }
    float mx = acc[0];
    #pragma unroll
    for (int k = 1; k < NEXP; k++) mx = fmaxf(mx, acc[k]);
    float sum = 0.f;
    #pragma unroll
    for (int k = 0; k < NEXP; k++) { acc[k] = expf(acc[k] - mx); sum += acc[k]; }
    float inv = 1.0f / sum;
    float* o = g_gw + ((size_t)b * Tn + t) * NEXP;
    #pragma unroll
    for (int k = 0; k < NEXP; k++) o[k] = acc[k] * inv;
}

// ---------------------------------------------------------------------------
// agg (fp16 out): aggh[b,t,:] = sum_k gw[b,t,k] * emb[b,k,:]
// ---------------------------------------------------------------------------
__global__ void agg_kernel() {
    int b = blockIdx.x;
    int e = threadIdx.x;
    __shared__ float sgw[Tn * NEXP];
    if (threadIdx.x < Tn * NEXP)
        sgw[threadIdx.x] = g_gw[(size_t)b * Tn * NEXP + threadIdx.x];
    __syncthreads();
    const float* eb = g_emb + (size_t)b * NEXP * En + e;
    float a0 = 0.f, a1 = 0.f, a2 = 0.f;
    #pragma unroll
    for (int k = 0; k < NEXP; k++) {
        float v = eb[(size_t)k * En];
        a0 += sgw[k] * v;
        a1 += sgw[NEXP + k] * v;
        a2 += sgw[2 * NEXP + k] * v;
    }
    __half* o = s_aggh + (size_t)b * Tn * En + e;
    o[0]      = __float2half_rn(a0);
    o[En]     = __float2half_rn(a1);
    o[2 * En] = __float2half_rn(a2);
}

// ---------------------------------------------------------------------------
extern "C" void kernel_launch(void* const* d_in, const int* in_sizes, int n_in,
                              void* d_out, int out_size) {
    const float* inputs = (const float*)d_in[0];
    const float* eW1 = (const float*)d_in[1];
    const float* eb1 = (const float*)d_in[2];
    const float* eW2 = (const float*)d_in[3];
    const float* eb2 = (const float*)d_in[4];
    const float* gW1 = (const float*)d_in[5];
    const float* gb1 = (const float*)d_in[6];
    const float* gW2 = (const float*)d_in[7];
    const float* gb2 = (const float*)d_in[8];
    const float* tW1 = (const float*)d_in[9];
    const float* tb1 = (const float*)d_in[10];
    const float* tW2 = (const float*)d_in[11];
    const float* tb2 = (const float*)d_in[12];
    float* out = (float*)d_out;

    __half *p_in, *p_gin, *p_h1, *p_we1, *p_we2, *p_wg1, *p_wt1, *p_aggh;
    float *p_emb, *p_gh, *p_th;
    cudaGetSymbolAddress((void**)&p_in,   s_in);
    cudaGetSymbolAddress((void**)&p_gin,  s_gin);
    cudaGetSymbolAddress((void**)&p_h1,   s_h1);
    cudaGetSymbolAddress((void**)&p_we1,  s_we1);
    cudaGetSymbolAddress((void**)&p_we2,  s_we2);
    cudaGetSymbolAddress((void**)&p_wg1,  s_wg1);
    cudaGetSymbolAddress((void**)&p_wt1,  s_wt1);
    cudaGetSymbolAddress((void**)&p_aggh, s_aggh);
    cudaGetSymbolAddress((void**)&p_emb,  g_emb);
    cudaGetSymbolAddress((void**)&p_gh,   g_gh);
    cudaGetSymbolAddress((void**)&p_th,   g_th);

    cudaFuncSetAttribute(tc_gemm, cudaFuncAttributeMaxDynamicSharedMemorySize, TC_SMEM);

    // ---- one fused conversion launch ----
    conv_all<<<(unsigned)(N_ALL / 256), 256>>>(inputs, eW1, eW2, gW1, tW1);

    // ---- expert layer 1: h1(fp16) = relu(in @ eW1 + b1) ----
    tc_gemm<<<dim3(Bn / 128, Hn / 128, NEXP), 256, TC_SMEM>>>(
        p_in, p_we1, eb1,
        nullptr, p_h1,
        Dn, Gn * Dn, Hn, NEXP * Hn,
        (long)Dn, NEn, (long)Dn * Hn, (long)Hn, (long)Hn, 1, 1);

    // ---- expert layer 2: emb(fp32) = h1 @ eW2 + b2 ----
    tc_gemm<<<dim3(Bn / 128, En / 128, NEXP), 256, TC_SMEM>>>(
        p_h1, p_we2, eb2,
        p_emb, nullptr,
        Hn, NEXP * Hn, En, NEXP * En,
        (long)Hn, 1, (long)Hn * En, (long)En, (long)En, 0, 0);

    // ---- gate layer 1: gh(fp32) = relu(gin @ gW1 + b1) ----
    tc_gemm<<<dim3(Bn / 128, GHn / 128, Tn), 256, TC_SMEM>>>(
        p_gin, p_wg1, gb1,
        p_gh, nullptr,
        Dn, Tn * Dn, GHn, Tn * GHn,
        (long)Dn, 1, (long)Dn * GHn, (long)GHn, (long)GHn, 1, 0);

    gate2_softmax_kernel<<<dim3(Bn / 256, Tn), 256>>>(gW2, gb2);

    agg_kernel<<<Bn, En>>>();

    // ---- tower layer 1 (tensor cores): th(fp32) = relu(aggh @ tW1 + b1) ----
    tc_gemm<<<dim3(Bn / 128, THn / 128, Tn), 256, TC_SMEM>>>(
        p_aggh, p_wt1, tb1,
        p_th, nullptr,
        En, Tn * En, THn, Tn * THn,
        (long)En, 1, (long)En * THn, (long)THn, (long)THn, 1, 0);

    // ---- tower layer 2 -> final output [B, T*TO] ----
    sgemm_bias<<<dim3(Bn / BM, 1, Tn), 256>>>(
        p_th, tW2, tb2, out,
        TOn, THn, Tn * THn, TOn, Tn * TOn,
        (long)THn, 1, (long)THn * TOn, (long)TOn, (long)TOn, 0);
}

// round 14
// speedup vs baseline: 1.4869x; 1.4869x over previous
#include <cuda_runtime.h>
#include <cuda_fp16.h>
#include <cstdint>
#include <math.h>

// Problem dims
#define Bn   16384
#define Tn   3
#define Dn   512
#define Gn   4
#define NEn  4
#define NEXP 16
#define Hn   512
#define En   256
#define GHn  256
#define THn  128
#define TOn  64

// ---------------- scratch (device globals; no allocs allowed) ----------------
__device__ __half s_in  [(size_t)Bn * Gn * Dn];
__device__ __half s_gin [(size_t)Bn * Tn * Dn];
__device__ __half s_h1  [(size_t)Bn * NEXP * Hn];
__device__ __half s_we1 [(size_t)NEXP * Dn * Hn];
__device__ __half s_we2 [(size_t)NEXP * Hn * En];
__device__ __half s_wg1 [(size_t)Tn * Dn * GHn];
__device__ __half s_wt1 [(size_t)Tn * En * THn];
__device__ __half s_aggh[(size_t)Bn * Tn * En];
__device__ float g_emb[(size_t)Bn * NEXP * En];
__device__ float g_gh [(size_t)Bn * Tn * GHn];
__device__ float g_gw [(size_t)Bn * Tn * NEXP];
__device__ float g_th [(size_t)Bn * Tn * THn];

// ---------------- helpers ----------------
__device__ __forceinline__ uint2 pack_h4(float4 v) {
    uint2 r;
    r.x = (unsigned)__half_as_ushort(__float2half_rn(v.x))
        | ((unsigned)__half_as_ushort(__float2half_rn(v.y)) << 16);
    r.y = (unsigned)__half_as_ushort(__float2half_rn(v.z))
        | ((unsigned)__half_as_ushort(__float2half_rn(v.w)) << 16);
    return r;
}

// ---------------- fused conversion kernel (all fp32->fp16 staging) ----------
#define N_IN  ((long)Bn * Gn * Dn / 4)
#define N_GIN ((long)Bn * Tn * Dn / 4)
#define N_E1  ((long)NEXP * Dn * Hn / 4)
#define N_E2  ((long)NEXP * Hn * En / 4)
#define N_G1  ((long)Tn * Dn * GHn / 4)
#define N_T1  ((long)Tn * En * THn / 4)
#define N_ALL (N_IN + N_GIN + N_E1 + N_E2 + N_G1 + N_T1)

__global__ void conv_all(const float* __restrict__ in,
                         const float* __restrict__ eW1, const float* __restrict__ eW2,
                         const float* __restrict__ gW1, const float* __restrict__ tW1) {
    long i = (long)blockIdx.x * blockDim.x + threadIdx.x;
    if (i < N_IN) {
        ((uint2*)s_in)[i] = pack_h4(((const float4*)in)[i]);
        return;
    }
    i -= N_IN;
    if (i < N_GIN) {
        int d4 = (int)(i % (Dn / 4));
        long bt = i / (Dn / 4);
        int t  = (int)(bt % Tn);
        long b = bt / Tn;
        const float4* base = (const float4*)(in + b * Gn * Dn);
        float4 a = base[(long)(t + 1) * (Dn / 4) + d4];
        float4 s = base[d4];
        ((uint2*)s_gin)[i] = pack_h4(make_float4(a.x + s.x, a.y + s.y, a.z + s.z, a.w + s.w));
        return;
    }
    i -= N_GIN;
    if (i < N_E1) { ((uint2*)s_we1)[i] = pack_h4(((const float4*)eW1)[i]); return; }
    i -= N_E1;
    if (i < N_E2) { ((uint2*)s_we2)[i] = pack_h4(((const float4*)eW2)[i]); return; }
    i -= N_E2;
    if (i < N_G1) { ((uint2*)s_wg1)[i] = pack_h4(((const float4*)gW1)[i]); return; }
    i -= N_G1;
    if (i < N_T1) { ((uint2*)s_wt1)[i] = pack_h4(((const float4*)tW1)[i]); }
}

// ===========================================================================
// Tensor-core batched GEMM: single fp16 A and B, register double-buffer.
// A [M,K] row-major; B [K,N] row-major. C = A@B + bias [+relu].
// Block tile 128x128x32, 256 threads (8 warps: 2M x 4N), warp tile 64x32.
// 2 CTAs/SM (smem 37.9KB/CTA).
// ===========================================================================
#define APITCH 40
#define BPITCH 136
#define A_OFF  0
#define B_OFF (128 * APITCH)                         // 5120
#define BUF_ELEMS (128 * APITCH + 32 * BPITCH)       // 9472
#define TC_SMEM (2 * BUF_ELEMS * 2)                  // 37888 bytes

__device__ __forceinline__ void mma_f16(float* c, const unsigned* a, const unsigned* b) {
    asm volatile(
        "mma.sync.aligned.m16n8k16.row.col.f32.f16.f16.f32 "
        "{%0,%1,%2,%3},{%4,%5,%6,%7},{%8,%9},{%0,%1,%2,%3};"
        : "+f"(c[0]), "+f"(c[1]), "+f"(c[2]), "+f"(c[3])
        : "r"(a[0]), "r"(a[1]), "r"(a[2]), "r"(a[3]), "r"(b[0]), "r"(b[1]));
}
__device__ __forceinline__ void ldsm4(unsigned& r0, unsigned& r1,
                                      unsigned& r2, unsigned& r3, unsigned addr) {
    asm volatile("ldmatrix.sync.aligned.m8n8.x4.shared.b16 {%0,%1,%2,%3},[%4];"
                 : "=r"(r0), "=r"(r1), "=r"(r2), "=r"(r3) : "r"(addr));
}
__device__ __forceinline__ void ldsm4t(unsigned& r0, unsigned& r1,
                                       unsigned& r2, unsigned& r3, unsigned addr) {
    asm volatile("ldmatrix.sync.aligned.m8n8.x4.trans.shared.b16 {%0,%1,%2,%3},[%4];"
                 : "=r"(r0), "=r"(r1), "=r"(r2), "=r"(r3) : "r"(addr));
}

__global__ void __launch_bounds__(256, 2)
tc_gemm(const __half* __restrict__ A, const __half* __restrict__ Bw,
        const float* __restrict__ bias,
        float* __restrict__ C, __half* __restrict__ Chalf,
        int K, int lda, int ldb, int ldc,
        long aStride, int aDiv, long bStride, long biasStride, long cStride,
        int relu, int halfOut)
{
    extern __shared__ __half sm[];
    int z = blockIdx.z;
    A  += (long)(z / aDiv) * aStride;
    Bw += (long)z * bStride;
    bias += (long)z * biasStride;
    if (halfOut) Chalf += (long)z * cStride;
    else         C     += (long)z * cStride;

    int tid  = threadIdx.x;
    int lane = tid & 31, warp = tid >> 5;
    int row0 = blockIdx.x * 128, col0 = blockIdx.y * 128;
    int wm = (warp >> 2) * 64, wn = (warp & 3) * 32;
    int g = lane >> 2, qt = lane & 3;

    unsigned sbase = (unsigned)__cvta_generic_to_shared(sm);

    // ldmatrix per-lane offsets
    int rA = (lane & 7) + ((lane >> 3) & 1) * 8;
    int cA = ((lane >> 4) & 1) * 8;
    int rB = (lane & 7) + ((lane >> 3) & 1) * 8;
    int cB = ((lane >> 4) & 1) * 8;

    // gmem load mapping
    int aRow = tid >> 2;            // 0..63 (+64)
    int aK8  = (tid & 3) * 8;
    int bK   = tid >> 3;            // 0..31
    int bN16 = (tid & 7) * 16;

    float acc[4][4][4];
    #pragma unroll
    for (int i = 0; i < 4; i++)
        #pragma unroll
        for (int j = 0; j < 4; j++)
            #pragma unroll
            for (int k = 0; k < 4; k++) acc[i][j][k] = 0.0f;

    const __half* aSrc0 = A + (long)(row0 + aRow) * lda + aK8;
    const __half* aSrc1 = A + (long)(row0 + aRow + 64) * lda + aK8;
    const __half* bSrc  = Bw + (long)bK * ldb + col0 + bN16;

    uint4 va0, va1, vb0, vb1;
    int nIter = K / 32;

    // prefetch tile 0
    va0 = *(const uint4*)(aSrc0);
    va1 = *(const uint4*)(aSrc1);
    vb0 = *(const uint4*)(bSrc);
    vb1 = *(const uint4*)(bSrc + 8);

    // store tile 0
    {
        __half* bp = sm;
        *(uint4*)(bp + A_OFF + aRow * APITCH + aK8)        = va0;
        *(uint4*)(bp + A_OFF + (aRow + 64) * APITCH + aK8) = va1;
        *(uint4*)(bp + B_OFF + bK * BPITCH + bN16)     = vb0;
        *(uint4*)(bp + B_OFF + bK * BPITCH + bN16 + 8) = vb1;
    }
    __syncthreads();

    int buf = 0;
    for (int it = 0; it < nIter; it++) {
        if (it + 1 < nIter) {
            int k0 = (it + 1) * 32;
            va0 = *(const uint4*)(aSrc0 + k0);
            va1 = *(const uint4*)(aSrc1 + k0);
            vb0 = *(const uint4*)(bSrc + (long)k0 * ldb);
            vb1 = *(const uint4*)(bSrc + (long)k0 * ldb + 8);
        }

        unsigned bufb = sbase + buf * (BUF_ELEMS * 2);

        #pragma unroll
        for (int ks = 0; ks < 32; ks += 16) {
            unsigned Af[4][4], Bf[4][2];
            #pragma unroll
            for (int mt = 0; mt < 4; mt++) {
                unsigned ad = bufb + (A_OFF + (wm + mt * 16 + rA) * APITCH + ks + cA) * 2;
                ldsm4(Af[mt][0], Af[mt][1], Af[mt][2], Af[mt][3], ad);
            }
            #pragma unroll
            for (int np = 0; np < 2; np++) {
                unsigned bd = bufb + (B_OFF + (ks + rB) * BPITCH + wn + np * 16 + cB) * 2;
                ldsm4t(Bf[2*np][0], Bf[2*np][1], Bf[2*np+1][0], Bf[2*np+1][1], bd);
            }
            #pragma unroll
            for (int mt = 0; mt < 4; mt++)
                #pragma unroll
                for (int nt = 0; nt < 4; nt++)
                    mma_f16(acc[mt][nt], Af[mt], Bf[nt]);
        }

        if (it + 1 < nIter) {
            __half* bp = sm + (buf ^ 1) * BUF_ELEMS;
            *(uint4*)(bp + A_OFF + aRow * APITCH + aK8)        = va0;
            *(uint4*)(bp + A_OFF + (aRow + 64) * APITCH + aK8) = va1;
            *(uint4*)(bp + B_OFF + bK * BPITCH + bN16)     = vb0;
            *(uint4*)(bp + B_OFF + bK * BPITCH + bN16 + 8) = vb1;
        }
        __syncthreads();
        buf ^= 1;
    }

    // epilogue
    #pragma unroll
    for (int mt = 0; mt < 4; mt++) {
        #pragma unroll
        for (int nt = 0; nt < 4; nt++) {
            int col = col0 + wn + nt * 8 + 2 * qt;
            long r0 = row0 + wm + mt * 16 + g;
            float b0v = bias[col], b1v = bias[col + 1];
            float2 v0 = make_float2(acc[mt][nt][0] + b0v, acc[mt][nt][1] + b1v);
            float2 v1 = make_float2(acc[mt][nt][2] + b0v, acc[mt][nt][3] + b1v);
            if (relu) {
                v0.x = fmaxf(v0.x, 0.f); v0.y = fmaxf(v0.y, 0.f);
                v1.x = fmaxf(v1.x, 0.f); v1.y = fmaxf(v1.y, 0.f);
            }
            if (halfOut) {
                *(unsigned*)(Chalf + r0 * ldc + col) =
                    (unsigned)__half_as_ushort(__float2half_rn(v0.x))
                  | ((unsigned)__half_as_ushort(__float2half_rn(v0.y)) << 16);
                *(unsigned*)(Chalf + (r0 + 8) * ldc + col) =
                    (unsigned)__half_as_ushort(__float2half_rn(v1.x))
                  | ((unsigned)__half_as_ushort(__float2half_rn(v1.y)) << 16);
            } else {
                *(float2*)&C[r0 * ldc + col] = v0;
                *(float2*)&C[(r0 + 8) * ldc + col] = v1;
            }
        }
    }
}

// ---------------------------------------------------------------------------
// Scalar FFMA SGEMM for tower layer 2 (N=64).
// ---------------------------------------------------------------------------
#define BM 128
#define BN 128
#define BK 8
#define TM 8
#define TN 8

__global__ __launch_bounds__(256)
void sgemm_bias(const float* __restrict__ A, const float* __restrict__ Bw,
                const float* __restrict__ bias, float* __restrict__ C,
                int N, int K, int lda, int ldb, int ldc,
                long aStride, int aDiv, long bStride, long biasStride, long cStride,
                int relu)
{
    int z = blockIdx.z;
    A    += (long)(z / aDiv) * aStride;
    Bw   += (long)z * bStride;
    bias += (long)z * biasStride;
    C    += (long)z * cStride;

    __shared__ float As[BK][BM];
    __shared__ float Bs[BK][BN];

    int tid  = threadIdx.x;
    int row0 = blockIdx.x * BM;
    int col0 = blockIdx.y * BN;
    int tx = tid % 16;
    int ty = tid / 16;

    int aRow = tid >> 1;
    int aCol = (tid & 1) * 4;
    int bRow = tid >> 5;
    int bCol = (tid & 31) * 4;
    bool bOk = (col0 + bCol) < N;

    float acc[TM][TN];
    #pragma unroll
    for (int i = 0; i < TM; i++)
        #pragma unroll
        for (int j = 0; j < TN; j++) acc[i][j] = 0.0f;

    for (int k0 = 0; k0 < K; k0 += BK) {
        float4 av = *(const float4*)&A[(long)(row0 + aRow) * lda + k0 + aCol];
        As[aCol + 0][aRow] = av.x;
        As[aCol + 1][aRow] = av.y;
        As[aCol + 2][aRow] = av.z;
        As[aCol + 3][aRow] = av.w;
        if (bOk) {
            float4 bv = *(const float4*)&Bw[(long)(k0 + bRow) * ldb + col0 + bCol];
            *(float4*)&Bs[bRow][bCol] = bv;
        }
        __syncthreads();

        #pragma unroll
        for (int kk = 0; kk < BK; kk++) {
            float4 a0 = *(const float4*)&As[kk][ty * TM];
            float4 a1 = *(const float4*)&As[kk][ty * TM + 4];
            float4 b0 = *(const float4*)&Bs[kk][tx * TN];
            float4 b1 = *(const float4*)&Bs[kk][tx * TN + 4];
            float ra[TM] = {a0.x, a0.y, a0.z, a0.w, a1.x, a1.y, a1.z, a1.w};
            float rbv[TN] = {b0.x, b0.y, b0.z, b0.w, b1.x, b1.y, b1.z, b1.w};
            #pragma unroll
            for (int i = 0; i < TM; i++)
                #pragma unroll
                for (int j = 0; j < TN; j++)
                    acc[i][j] += ra[i] * rbv[j];
        }
        __syncthreads();
    }

    #pragma unroll
    for (int i = 0; i < TM; i++) {
        long rr = row0 + ty * TM + i;
        #pragma unroll
        for (int j0 = 0; j0 < TN; j0 += 4) {
            int c = col0 + tx * TN + j0;
            if (c < N) {
                float4 v;
                v.x = acc[i][j0 + 0] + bias[c + 0];
                v.y = acc[i][j0 + 1] + bias[c + 1];
                v.z = acc[i][j0 + 2] + bias[c + 2];
                v.w = acc[i][j0 + 3] + bias[c + 3];
                if (relu) {
                    v.x = fmaxf(v.x, 0.f); v.y = fmaxf(v.y, 0.f);
                    v.z = fmaxf(v.z, 0.f); v.w = fmaxf(v.w, 0.f);
                }
                *(float4*)&C[rr * ldc + c] = v;
            }
        }
    }
}

// ---------------------------------------------------------------------------
__global__ void gate2_softmax_kernel(const float* __restrict__ W2,
                                     const float* __restrict__ b2) {
    int t = blockIdx.y;
    __shared__ float sW[GHn * NEXP];
    __shared__ float sb[NEXP];
    for (int i = threadIdx.x; i < GHn * NEXP; i += blockDim.x)
        sW[i] = W2[(size_t)t * GHn * NEXP + i];
    if (threadIdx.x < NEXP) sb[threadIdx.x] = b2[t * NEXP + threadIdx.x];
    __syncthreads();

    int b = blockIdx.x * blockDim.x + threadIdx.x;
    if (b >= Bn) return;

    const float4* gr = (const float4*)(g_gh + ((size_t)b * Tn + t) * GHn);
    float acc[NEXP];
    #pragma unroll
    for (int k = 0; k < NEXP; k++) acc[k] = sb[k];
    for (int h4 = 0; h4 < GHn / 4; h4++) {
        float4 x = gr[h4];
        const float* w = sW + h4 * 4 * NEXP;
        #pragma unroll
        for (int k = 0; k < NEXP; k++)
            acc[k] += x.x * w[k] + x.y * w[NEXP + k]
                    + x.z * w[2 * NEXP + k] + x.w * w[3 * NEXP + k];
    }
    float mx = acc[0];
    #pragma unroll
    for (int k = 1; k < NEXP; k++) mx = fmaxf(mx, acc[k]);
    float sum = 0.f;
    #pragma unroll
    for (int k = 0; k < NEXP; k++) { acc[k] = expf(acc[k] - mx); sum += acc[k]; }
    float inv = 1.0f / sum;
    float* o = g_gw + ((size_t)b * Tn + t) * NEXP;
    #pragma unroll
    for (int k = 0; k < NEXP; k++) o[k] = acc[k] * inv;
}

// ---------------------------------------------------------------------------
// agg (fp16 out): aggh[b,t,:] = sum_k gw[b,t,k] * emb[b,k,:]
// ---------------------------------------------------------------------------
__global__ void agg_kernel() {
    int b = blockIdx.x;
    int e = threadIdx.x;
    __shared__ float sgw[Tn * NEXP];
    if (threadIdx.x < Tn * NEXP)
        sgw[threadIdx.x] = g_gw[(size_t)b * Tn * NEXP + threadIdx.x];
    __syncthreads();
    const float* eb = g_emb + (size_t)b * NEXP * En + e;
    float a0 = 0.f, a1 = 0.f, a2 = 0.f;
    #pragma unroll
    for (int k = 0; k < NEXP; k++) {
        float v = eb[(size_t)k * En];
        a0 += sgw[k] * v;
        a1 += sgw[NEXP + k] * v;
        a2 += sgw[2 * NEXP + k] * v;
    }
    __half* o = s_aggh + (size_t)b * Tn * En + e;
    o[0]      = __float2half_rn(a0);
    o[En]     = __float2half_rn(a1);
    o[2 * En] = __float2half_rn(a2);
}

// ---------------------------------------------------------------------------
extern "C" void kernel_launch(void* const* d_in, const int* in_sizes, int n_in,
                              void* d_out, int out_size) {
    const float* inputs = (const float*)d_in[0];
    const float* eW1 = (const float*)d_in[1];
    const float* eb1 = (const float*)d_in[2];
    const float* eW2 = (const float*)d_in[3];
    const float* eb2 = (const float*)d_in[4];
    const float* gW1 = (const float*)d_in[5];
    const float* gb1 = (const float*)d_in[6];
    const float* gW2 = (const float*)d_in[7];
    const float* gb2 = (const float*)d_in[8];
    const float* tW1 = (const float*)d_in[9];
    const float* tb1 = (const float*)d_in[10];
    const float* tW2 = (const float*)d_in[11];
    const float* tb2 = (const float*)d_in[12];
    float* out = (float*)d_out;

    __half *p_in, *p_gin, *p_h1, *p_we1, *p_we2, *p_wg1, *p_wt1, *p_aggh;
    float *p_emb, *p_gh, *p_th;
    cudaGetSymbolAddress((void**)&p_in,   s_in);
    cudaGetSymbolAddress((void**)&p_gin,  s_gin);
    cudaGetSymbolAddress((void**)&p_h1,   s_h1);
    cudaGetSymbolAddress((void**)&p_we1,  s_we1);
    cudaGetSymbolAddress((void**)&p_we2,  s_we2);
    cudaGetSymbolAddress((void**)&p_wg1,  s_wg1);
    cudaGetSymbolAddress((void**)&p_wt1,  s_wt1);
    cudaGetSymbolAddress((void**)&p_aggh, s_aggh);
    cudaGetSymbolAddress((void**)&p_emb,  g_emb);
    cudaGetSymbolAddress((void**)&p_gh,   g_gh);
    cudaGetSymbolAddress((void**)&p_th,   g_th);

    cudaFuncSetAttribute(tc_gemm, cudaFuncAttributeMaxDynamicSharedMemorySize, TC_SMEM);

    // ---- one fused conversion launch ----
    conv_all<<<(unsigned)(N_ALL / 256), 256>>>(inputs, eW1, eW2, gW1, tW1);

    // ---- expert layer 1: h1(fp16) = relu(in @ eW1 + b1) ----
    tc_gemm<<<dim3(Bn / 128, Hn / 128, NEXP), 256, TC_SMEM>>>(
        p_in, p_we1, eb1,
        nullptr, p_h1,
        Dn, Gn * Dn, Hn, NEXP * Hn,
        (long)Dn, NEn, (long)Dn * Hn, (long)Hn, (long)Hn, 1, 1);

    // ---- expert layer 2: emb(fp32) = h1 @ eW2 + b2 ----
    tc_gemm<<<dim3(Bn / 128, En / 128, NEXP), 256, TC_SMEM>>>(
        p_h1, p_we2, eb2,
        p_emb, nullptr,
        Hn, NEXP * Hn, En, NEXP * En,
        (long)Hn, 1, (long)Hn * En, (long)En, (long)En, 0, 0);

    // ---- gate layer 1: gh(fp32) = relu(gin @ gW1 + b1) ----
    tc_gemm<<<dim3(Bn / 128, GHn / 128, Tn), 256, TC_SMEM>>>(
        p_gin, p_wg1, gb1,
        p_gh, nullptr,
        Dn, Tn * Dn, GHn, Tn * GHn,
        (long)Dn, 1, (long)Dn * GHn, (long)GHn, (long)GHn, 1, 0);

    gate2_softmax_kernel<<<dim3(Bn / 256, Tn), 256>>>(gW2, gb2);

    agg_kernel<<<Bn, En>>>();

    // ---- tower layer 1 (tensor cores): th(fp32) = relu(aggh @ tW1 + b1) ----
    tc_gemm<<<dim3(Bn / 128, THn / 128, Tn), 256, TC_SMEM>>>(
        p_aggh, p_wt1, tb1,
        p_th, nullptr,
        En, Tn * En, THn, Tn * THn,
        (long)En, 1, (long)En * THn, (long)THn, (long)THn, 1, 0);

    // ---- tower layer 2 -> final output [B, T*TO] ----
    sgemm_bias<<<dim3(Bn / BM, 1, Tn), 256>>>(
        p_th, tW2, tb2, out,
        TOn, THn, Tn * THn, TOn, Tn * TOn,
        (long)THn, 1, (long)THn * TOn, (long)TOn, (long)TOn, 0);
}

// round 15
// speedup vs baseline: 1.5250x; 1.0256x over previous
#include <cuda_runtime.h>
#include <cuda_fp16.h>
#include <cstdint>
#include <math.h>

// Problem dims
#define Bn   16384
#define Tn   3
#define Dn   512
#define Gn   4
#define NEn  4
#define NEXP 16
#define Hn   512
#define En   256
#define GHn  256
#define THn  128
#define TOn  64

// ---------------- scratch (device globals; no allocs allowed) ----------------
__device__ __half s_in  [(size_t)Bn * Gn * Dn];
__device__ __half s_gin [(size_t)Bn * Tn * Dn];
__device__ __half s_h1  [(size_t)Bn * NEXP * Hn];
__device__ __half s_embh[(size_t)Bn * NEXP * En];
__device__ __half s_we1 [(size_t)NEXP * Dn * Hn];
__device__ __half s_we2 [(size_t)NEXP * Hn * En];
__device__ __half s_wg1 [(size_t)Tn * Dn * GHn];
__device__ __half s_wt1 [(size_t)Tn * En * THn];
__device__ __half s_aggh[(size_t)Bn * Tn * En];
__device__ float g_gh [(size_t)Bn * Tn * GHn];
__device__ float g_gw [(size_t)Bn * Tn * NEXP];
__device__ float g_th [(size_t)Bn * Tn * THn];

// ---------------- helpers ----------------
__device__ __forceinline__ uint2 pack_h4(float4 v) {
    uint2 r;
    r.x = (unsigned)__half_as_ushort(__float2half_rn(v.x))
        | ((unsigned)__half_as_ushort(__float2half_rn(v.y)) << 16);
    r.y = (unsigned)__half_as_ushort(__float2half_rn(v.z))
        | ((unsigned)__half_as_ushort(__float2half_rn(v.w)) << 16);
    return r;
}

// ---------------- fused conversion kernel ----------------
#define N_IN  ((long)Bn * Gn * Dn / 4)
#define N_GIN ((long)Bn * Tn * Dn / 4)
#define N_E1  ((long)NEXP * Dn * Hn / 4)
#define N_E2  ((long)NEXP * Hn * En / 4)
#define N_G1  ((long)Tn * Dn * GHn / 4)
#define N_T1  ((long)Tn * En * THn / 4)
#define N_ALL (N_IN + N_GIN + N_E1 + N_E2 + N_G1 + N_T1)

__global__ void conv_all(const float* __restrict__ in,
                         const float* __restrict__ eW1, const float* __restrict__ eW2,
                         const float* __restrict__ gW1, const float* __restrict__ tW1) {
    long i = (long)blockIdx.x * blockDim.x + threadIdx.x;
    if (i < N_IN) {
        ((uint2*)s_in)[i] = pack_h4(((const float4*)in)[i]);
        return;
    }
    i -= N_IN;
    if (i < N_GIN) {
        int d4 = (int)(i % (Dn / 4));
        long bt = i / (Dn / 4);
        int t  = (int)(bt % Tn);
        long b = bt / Tn;
        const float4* base = (const float4*)(in + b * Gn * Dn);
        float4 a = base[(long)(t + 1) * (Dn / 4) + d4];
        float4 s = base[d4];
        ((uint2*)s_gin)[i] = pack_h4(make_float4(a.x + s.x, a.y + s.y, a.z + s.z, a.w + s.w));
        return;
    }
    i -= N_GIN;
    if (i < N_E1) { ((uint2*)s_we1)[i] = pack_h4(((const float4*)eW1)[i]); return; }
    i -= N_E1;
    if (i < N_E2) { ((uint2*)s_we2)[i] = pack_h4(((const float4*)eW2)[i]); return; }
    i -= N_E2;
    if (i < N_G1) { ((uint2*)s_wg1)[i] = pack_h4(((const float4*)gW1)[i]); return; }
    i -= N_G1;
    if (i < N_T1) { ((uint2*)s_wt1)[i] = pack_h4(((const float4*)tW1)[i]); }
}

// ===========================================================================
// Shared GEMM body (proven R12 mainloop): fp16 A,B; register double-buffer;
// block tile 128x128x32; 256 threads (2M x 4N warps), warp tile 64x32.
// ===========================================================================
#define APITCH 40
#define BPITCH 136
#define A_OFF  0
#define B_OFF (128 * APITCH)
#define BUF_ELEMS (128 * APITCH + 32 * BPITCH)       // 9472
#define TC_SMEM (2 * BUF_ELEMS * 2)                  // 37888 bytes

__device__ __forceinline__ void mma_f16(float* c, const unsigned* a, const unsigned* b) {
    asm volatile(
        "mma.sync.aligned.m16n8k16.row.col.f32.f16.f16.f32 "
        "{%0,%1,%2,%3},{%4,%5,%6,%7},{%8,%9},{%0,%1,%2,%3};"
        : "+f"(c[0]), "+f"(c[1]), "+f"(c[2]), "+f"(c[3])
        : "r"(a[0]), "r"(a[1]), "r"(a[2]), "r"(a[3]), "r"(b[0]), "r"(b[1]));
}
__device__ __forceinline__ void ldsm4(unsigned& r0, unsigned& r1,
                                      unsigned& r2, unsigned& r3, unsigned addr) {
    asm volatile("ldmatrix.sync.aligned.m8n8.x4.shared.b16 {%0,%1,%2,%3},[%4];"
                 : "=r"(r0), "=r"(r1), "=r"(r2), "=r"(r3) : "r"(addr));
}
__device__ __forceinline__ void ldsm4t(unsigned& r0, unsigned& r1,
                                       unsigned& r2, unsigned& r3, unsigned addr) {
    asm volatile("ldmatrix.sync.aligned.m8n8.x4.trans.shared.b16 {%0,%1,%2,%3},[%4];"
                 : "=r"(r0), "=r"(r1), "=r"(r2), "=r"(r3) : "r"(addr));
}

__device__ __forceinline__ void gemm_body(
        const __half* __restrict__ A, const __half* __restrict__ Bw,
        const float* __restrict__ bias,
        float* __restrict__ C, __half* __restrict__ Chalf,
        int K, int lda, int ldb, int ldc, int relu, int halfOut)
{
    extern __shared__ __half sm[];
    int tid  = threadIdx.x;
    int lane = tid & 31, warp = tid >> 5;
    int row0 = blockIdx.x * 128, col0 = blockIdx.y * 128;
    int wm = (warp >> 2) * 64, wn = (warp & 3) * 32;
    int g = lane >> 2, qt = lane & 3;

    unsigned sbase = (unsigned)__cvta_generic_to_shared(sm);

    int rA = (lane & 7) + ((lane >> 3) & 1) * 8;
    int cA = ((lane >> 4) & 1) * 8;
    int rB = (lane & 7) + ((lane >> 3) & 1) * 8;
    int cB = ((lane >> 4) & 1) * 8;

    int aRow = tid >> 2;
    int aK8  = (tid & 3) * 8;
    int bK   = tid >> 3;
    int bN16 = (tid & 7) * 16;

    float acc[4][4][4];
    #pragma unroll
    for (int i = 0; i < 4; i++)
        #pragma unroll
        for (int j = 0; j < 4; j++)
            #pragma unroll
            for (int k = 0; k < 4; k++) acc[i][j][k] = 0.0f;

    const __half* aSrc0 = A + (long)(row0 + aRow) * lda + aK8;
    const __half* aSrc1 = A + (long)(row0 + aRow + 64) * lda + aK8;
    const __half* bSrc  = Bw + (long)bK * ldb + col0 + bN16;

    uint4 va0, va1, vb0, vb1;
    int nIter = K / 32;

    va0 = *(const uint4*)(aSrc0);
    va1 = *(const uint4*)(aSrc1);
    vb0 = *(const uint4*)(bSrc);
    vb1 = *(const uint4*)(bSrc + 8);

    {
        __half* bp = sm;
        *(uint4*)(bp + A_OFF + aRow * APITCH + aK8)        = va0;
        *(uint4*)(bp + A_OFF + (aRow + 64) * APITCH + aK8) = va1;
        *(uint4*)(bp + B_OFF + bK * BPITCH + bN16)     = vb0;
        *(uint4*)(bp + B_OFF + bK * BPITCH + bN16 + 8) = vb1;
    }
    __syncthreads();

    int buf = 0;
    for (int it = 0; it < nIter; it++) {
        if (it + 1 < nIter) {
            int k0 = (it + 1) * 32;
            va0 = *(const uint4*)(aSrc0 + k0);
            va1 = *(const uint4*)(aSrc1 + k0);
            vb0 = *(const uint4*)(bSrc + (long)k0 * ldb);
            vb1 = *(const uint4*)(bSrc + (long)k0 * ldb + 8);
        }

        unsigned bufb = sbase + buf * (BUF_ELEMS * 2);

        #pragma unroll
        for (int ks = 0; ks < 32; ks += 16) {
            unsigned Af[4][4], Bf[4][2];
            #pragma unroll
            for (int mt = 0; mt < 4; mt++) {
                unsigned ad = bufb + (A_OFF + (wm + mt * 16 + rA) * APITCH + ks + cA) * 2;
                ldsm4(Af[mt][0], Af[mt][1], Af[mt][2], Af[mt][3], ad);
            }
            #pragma unroll
            for (int np = 0; np < 2; np++) {
                unsigned bd = bufb + (B_OFF + (ks + rB) * BPITCH + wn + np * 16 + cB) * 2;
                ldsm4t(Bf[2*np][0], Bf[2*np][1], Bf[2*np+1][0], Bf[2*np+1][1], bd);
            }
            #pragma unroll
            for (int mt = 0; mt < 4; mt++)
                #pragma unroll
                for (int nt = 0; nt < 4; nt++)
                    mma_f16(acc[mt][nt], Af[mt], Bf[nt]);
        }

        if (it + 1 < nIter) {
            __half* bp = sm + (buf ^ 1) * BUF_ELEMS;
            *(uint4*)(bp + A_OFF + aRow * APITCH + aK8)        = va0;
            *(uint4*)(bp + A_OFF + (aRow + 64) * APITCH + aK8) = va1;
            *(uint4*)(bp + B_OFF + bK * BPITCH + bN16)     = vb0;
            *(uint4*)(bp + B_OFF + bK * BPITCH + bN16 + 8) = vb1;
        }
        __syncthreads();
        buf ^= 1;
    }

    #pragma unroll
    for (int mt = 0; mt < 4; mt++) {
        #pragma unroll
        for (int nt = 0; nt < 4; nt++) {
            int col = col0 + wn + nt * 8 + 2 * qt;
            long r0 = row0 + wm + mt * 16 + g;
            float b0v = bias[col], b1v = bias[col + 1];
            float2 v0 = make_float2(acc[mt][nt][0] + b0v, acc[mt][nt][1] + b1v);
            float2 v1 = make_float2(acc[mt][nt][2] + b0v, acc[mt][nt][3] + b1v);
            if (relu) {
                v0.x = fmaxf(v0.x, 0.f); v0.y = fmaxf(v0.y, 0.f);
                v1.x = fmaxf(v1.x, 0.f); v1.y = fmaxf(v1.y, 0.f);
            }
            if (halfOut) {
                *(unsigned*)(Chalf + r0 * ldc + col) =
                    (unsigned)__half_as_ushort(__float2half_rn(v0.x))
                  | ((unsigned)__half_as_ushort(__float2half_rn(v0.y)) << 16);
                *(unsigned*)(Chalf + (r0 + 8) * ldc + col) =
                    (unsigned)__half_as_ushort(__float2half_rn(v1.x))
                  | ((unsigned)__half_as_ushort(__float2half_rn(v1.y)) << 16);
            } else {
                *(float2*)&C[r0 * ldc + col] = v0;
                *(float2*)&C[(r0 + 8) * ldc + col] = v1;
            }
        }
    }
}

// ---- generic batched GEMM (expert L2, tower1) ----
__global__ void __launch_bounds__(256, 2)
tc_gemm(const __half* __restrict__ A, const __half* __restrict__ Bw,
        const float* __restrict__ bias,
        float* __restrict__ C, __half* __restrict__ Chalf,
        int K, int lda, int ldb, int ldc,
        long aStride, int aDiv, long bStride, long biasStride, long cStride,
        int relu, int halfOut)
{
    int z = blockIdx.z;
    A  += (long)(z / aDiv) * aStride;
    Bw += (long)z * bStride;
    bias += (long)z * biasStride;
    if (halfOut) Chalf += (long)z * cStride;
    else         C     += (long)z * cStride;
    gemm_body(A, Bw, bias, C, Chalf, K, lda, ldb, ldc, relu, halfOut);
}

// ---- merged expert-L1 (z=0..15) + gate-L1 (z=16..18) launch ----
__global__ void __launch_bounds__(256, 2)
tc_gemm_l1g1(const float* __restrict__ eb1, const float* __restrict__ gb1)
{
    int z = blockIdx.z;
    if (z < NEXP) {
        // expert layer 1: h1[.,z,:] = relu(in[., z/4, :] @ eW1[z] + eb1[z]) -> fp16
        gemm_body(s_in + (long)(z / NEn) * Dn,
                  s_we1 + (long)z * Dn * Hn,
                  eb1 + (long)z * Hn,
                  nullptr, s_h1 + (long)z * Hn,
                  Dn, Gn * Dn, Hn, NEXP * Hn, 1, 1);
    } else {
        if (blockIdx.y >= GHn / 128) return;   // gates: N=256 -> only y=0,1
        int t = z - NEXP;
        // gate layer 1: gh[.,t,:] = relu(gin[.,t,:] @ gW1[t] + gb1[t]) -> fp32
        gemm_body(s_gin + (long)t * Dn,
                  s_wg1 + (long)t * Dn * GHn,
                  gb1 + (long)t * GHn,
                  g_gh + (long)t * GHn, nullptr,
                  Dn, Tn * Dn, GHn, Tn * GHn, 1, 0);
    }
}

// ---------------------------------------------------------------------------
// Scalar FFMA SGEMM for tower layer 2 (N=64).
// ---------------------------------------------------------------------------
#define BM 128
#define BN 128
#define BK 8
#define TM 8
#define TN 8

__global__ __launch_bounds__(256)
void sgemm_bias(const float* __restrict__ A, const float* __restrict__ Bw,
                const float* __restrict__ bias, float* __restrict__ C,
                int N, int K, int lda, int ldb, int ldc,
                long aStride, int aDiv, long bStride, long biasStride, long cStride,
                int relu)
{
    int z = blockIdx.z;
    A    += (long)(z / aDiv) * aStride;
    Bw   += (long)z * bStride;
    bias += (long)z * biasStride;
    C    += (long)z * cStride;

    __shared__ float As[BK][BM];
    __shared__ float Bs[BK][BN];

    int tid  = threadIdx.x;
    int row0 = blockIdx.x * BM;
    int col0 = blockIdx.y * BN;
    int tx = tid % 16;
    int ty = tid / 16;

    int aRow = tid >> 1;
    int aCol = (tid & 1) * 4;
    int bRow = tid >> 5;
    int bCol = (tid & 31) * 4;
    bool bOk = (col0 + bCol) < N;

    float acc[TM][TN];
    #pragma unroll
    for (int i = 0; i < TM; i++)
        #pragma unroll
        for (int j = 0; j < TN; j++) acc[i][j] = 0.0f;

    for (int k0 = 0; k0 < K; k0 += BK) {
        float4 av = *(const float4*)&A[(long)(row0 + aRow) * lda + k0 + aCol];
        As[aCol + 0][aRow] = av.x;
        As[aCol + 1][aRow] = av.y;
        As[aCol + 2][aRow] = av.z;
        As[aCol + 3][aRow] = av.w;
        if (bOk) {
            float4 bv = *(const float4*)&Bw[(long)(k0 + bRow) * ldb + col0 + bCol];
            *(float4*)&Bs[bRow][bCol] = bv;
        }
        __syncthreads();

        #pragma unroll
        for (int kk = 0; kk < BK; kk++) {
            float4 a0 = *(const float4*)&As[kk][ty * TM];
            float4 a1 = *(const float4*)&As[kk][ty * TM + 4];
            float4 b0 = *(const float4*)&Bs[kk][tx * TN];
            float4 b1 = *(const float4*)&Bs[kk][tx * TN + 4];
            float ra[TM] = {a0.x, a0.y, a0.z, a0.w, a1.x, a1.y, a1.z, a1.w};
            float rbv[TN] = {b0.x, b0.y, b0.z, b0.w, b1.x, b1.y, b1.z, b1.w};
            #pragma unroll
            for (int i = 0; i < TM; i++)
                #pragma unroll
                for (int j = 0; j < TN; j++)
                    acc[i][j] += ra[i] * rbv[j];
        }
        __syncthreads();
    }

    #pragma unroll
    for (int i = 0; i < TM; i++) {
        long rr = row0 + ty * TM + i;
        #pragma unroll
        for (int j0 = 0; j0 < TN; j0 += 4) {
            int c = col0 + tx * TN + j0;
            if (c < N) {
                float4 v;
                v.x = acc[i][j0 + 0] + bias[c + 0];
                v.y = acc[i][j0 + 1] + bias[c + 1];
                v.z = acc[i][j0 + 2] + bias[c + 2];
                v.w = acc[i][j0 + 3] + bias[c + 3];
                if (relu) {
                    v.x = fmaxf(v.x, 0.f); v.y = fmaxf(v.y, 0.f);
                    v.z = fmaxf(v.z, 0.f); v.w = fmaxf(v.w, 0.f);
                }
                *(float4*)&C[rr * ldc + c] = v;
            }
        }
    }
}

// ---------------------------------------------------------------------------
__global__ void gate2_softmax_kernel(const float* __restrict__ W2,
                                     const float* __restrict__ b2) {
    int t = blockIdx.y;
    __shared__ float sW[GHn * NEXP];
    __shared__ float sb[NEXP];
    for (int i = threadIdx.x; i < GHn * NEXP; i += blockDim.x)
        sW[i] = W2[(size_t)t * GHn * NEXP + i];
    if (threadIdx.x < NEXP) sb[threadIdx.x] = b2[t * NEXP + threadIdx.x];
    __syncthreads();

    int b = blockIdx.x * blockDim.x + threadIdx.x;
    if (b >= Bn) return;

    const float4* gr = (const float4*)(g_gh + ((size_t)b * Tn + t) * GHn);
    float acc[NEXP];
    #pragma unroll
    for (int k = 0; k < NEXP; k++) acc[k] = sb[k];
    for (int h4 = 0; h4 < GHn / 4; h4++) {
        float4 x = gr[h4];
        const float* w = sW + h4 * 4 * NEXP;
        #pragma unroll
        for (int k = 0; k < NEXP; k++)
            acc[k] += x.x * w[k] + x.y * w[NEXP + k]
                    + x.z * w[2 * NEXP + k] + x.w * w[3 * NEXP + k];
    }
    float mx = acc[0];
    #pragma unroll
    for (int k = 1; k < NEXP; k++) mx = fmaxf(mx, acc[k]);
    float sum = 0.f;
    #pragma unroll
    for (int k = 0; k < NEXP; k++) { acc[k] = expf(acc[k] - mx); sum += acc[k]; }
    float inv = 1.0f / sum;
    float* o = g_gw + ((size_t)b * Tn + t) * NEXP;
    #pragma unroll
    for (int k = 0; k < NEXP; k++) o[k] = acc[k] * inv;
}

// ---------------------------------------------------------------------------
// agg (fp16 in/out): aggh[b,t,:] = sum_k gw[b,t,k] * embh[b,k,:]
// ---------------------------------------------------------------------------
__global__ void agg_kernel() {
    int b = blockIdx.x;
    int e = threadIdx.x;
    __shared__ float sgw[Tn * NEXP];
    if (threadIdx.x < Tn * NEXP)
        sgw[threadIdx.x] = g_gw[(size_t)b * Tn * NEXP + threadIdx.x];
    __syncthreads();
    const __half* eb = s_embh + (size_t)b * NEXP * En + e;
    float a0 = 0.f, a1 = 0.f, a2 = 0.f;
    #pragma unroll
    for (int k = 0; k < NEXP; k++) {
        float v = __half2float(eb[(size_t)k * En]);
        a0 += sgw[k] * v;
        a1 += sgw[NEXP + k] * v;
        a2 += sgw[2 * NEXP + k] * v;
    }
    __half* o = s_aggh + (size_t)b * Tn * En + e;
    o[0]      = __float2half_rn(a0);
    o[En]     = __float2half_rn(a1);
    o[2 * En] = __float2half_rn(a2);
}

// ---------------------------------------------------------------------------
extern "C" void kernel_launch(void* const* d_in, const int* in_sizes, int n_in,
                              void* d_out, int out_size) {
    const float* inputs = (const float*)d_in[0];
    const float* eW1 = (const float*)d_in[1];
    const float* eb1 = (const float*)d_in[2];
    const float* eW2 = (const float*)d_in[3];
    const float* eb2 = (const float*)d_in[4];
    const float* gW1 = (const float*)d_in[5];
    const float* gb1 = (const float*)d_in[6];
    const float* gW2 = (const float*)d_in[7];
    const float* gb2 = (const float*)d_in[8];
    const float* tW1 = (const float*)d_in[9];
    const float* tb1 = (const float*)d_in[10];
    const float* tW2 = (const float*)d_in[11];
    const float* tb2 = (const float*)d_in[12];
    float* out = (float*)d_out;

    __half *p_h1, *p_embh, *p_we2, *p_wt1, *p_aggh;
    float *p_th;
    cudaGetSymbolAddress((void**)&p_h1,   s_h1);
    cudaGetSymbolAddress((void**)&p_embh, s_embh);
    cudaGetSymbolAddress((void**)&p_we2,  s_we2);
    cudaGetSymbolAddress((void**)&p_wt1,  s_wt1);
    cudaGetSymbolAddress((void**)&p_aggh, s_aggh);
    cudaGetSymbolAddress((void**)&p_th,   g_th);
    __half *p_wt1b; // silence unused warnings pattern
    (void)p_wt1b;

    cudaFuncSetAttribute(tc_gemm, cudaFuncAttributeMaxDynamicSharedMemorySize, TC_SMEM);
    cudaFuncSetAttribute(tc_gemm_l1g1, cudaFuncAttributeMaxDynamicSharedMemorySize, TC_SMEM);

    // ---- one fused conversion launch ----
    conv_all<<<(unsigned)(N_ALL / 256), 256>>>(inputs, eW1, eW2, gW1, tW1);

    // ---- merged expert L1 + gate L1 ----
    tc_gemm_l1g1<<<dim3(Bn / 128, Hn / 128, NEXP + Tn), 256, TC_SMEM>>>(eb1, gb1);

    // ---- expert layer 2: embh(fp16) = h1 @ eW2 + b2 ----
    tc_gemm<<<dim3(Bn / 128, En / 128, NEXP), 256, TC_SMEM>>>(
        p_h1, p_we2, eb2,
        nullptr, p_embh,
        Hn, NEXP * Hn, En, NEXP * En,
        (long)Hn, 1, (long)Hn * En, (long)En, (long)En, 0, 1);

    gate2_softmax_kernel<<<dim3(Bn / 256, Tn), 256>>>(gW2, gb2);

    agg_kernel<<<Bn, En>>>();

    // ---- tower layer 1 (tensor cores): th(fp32) = relu(aggh @ tW1 + b1) ----
    tc_gemm<<<dim3(Bn / 128, THn / 128, Tn), 256, TC_SMEM>>>(
        p_aggh, p_wt1, tb1,
        p_th, nullptr,
        En, Tn * En, THn, Tn * THn,
        (long)En, 1, (long)En * THn, (long)THn, (long)THn, 1, 0);

    // ---- tower layer 2 -> final output [B, T*TO] ----
    sgemm_bias<<<dim3(Bn / BM, 1, Tn), 256>>>(
        p_th, tW2, tb2, out,
        TOn, THn, Tn * THn, TOn, Tn * TOn,
        (long)THn, 1, (long)THn * TOn, (long)TOn, (long)TOn, 0);
}

// round 17
// speedup vs baseline: 1.5335x; 1.0056x over previous
#include <cuda_runtime.h>
#include <cuda_fp16.h>
#include <cstdint>
#include <math.h>

// Problem dims
#define Bn   16384
#define Tn   3
#define Dn   512
#define Gn   4
#define NEn  4
#define NEXP 16
#define Hn   512
#define En   256
#define GHn  256
#define THn  128
#define TOn  64

// ---------------- scratch (device globals; no allocs allowed) ----------------
__device__ __half s_in  [(size_t)Bn * Gn * Dn];
__device__ __half s_gin [(size_t)Bn * Tn * Dn];
__device__ __half s_h1  [(size_t)Bn * NEXP * Hn];
__device__ __half s_embh[(size_t)Bn * NEXP * En];
__device__ __half s_we1 [(size_t)NEXP * Dn * Hn];
__device__ __half s_we2 [(size_t)NEXP * Hn * En];
__device__ __half s_wg1 [(size_t)Tn * Dn * GHn];
__device__ __half s_wt1 [(size_t)Tn * En * THn];
__device__ __half s_aggh[(size_t)Bn * Tn * En];
__device__ float g_gh [(size_t)Bn * Tn * GHn];
__device__ float g_gw [(size_t)Bn * Tn * NEXP];
__device__ float g_th [(size_t)Bn * Tn * THn];

// ---------------- helpers ----------------
__device__ __forceinline__ uint2 pack_h4(float4 v) {
    uint2 r;
    r.x = (unsigned)__half_as_ushort(__float2half_rn(v.x))
        | ((unsigned)__half_as_ushort(__float2half_rn(v.y)) << 16);
    r.y = (unsigned)__half_as_ushort(__float2half_rn(v.z))
        | ((unsigned)__half_as_ushort(__float2half_rn(v.w)) << 16);
    return r;
}

// ---------------- fused conversion kernel ----------------
#define N_IN  ((long)Bn * Gn * Dn / 4)
#define N_GIN ((long)Bn * Tn * Dn / 4)
#define N_E1  ((long)NEXP * Dn * Hn / 4)
#define N_E2  ((long)NEXP * Hn * En / 4)
#define N_G1  ((long)Tn * Dn * GHn / 4)
#define N_T1  ((long)Tn * En * THn / 4)
#define N_ALL (N_IN + N_GIN + N_E1 + N_E2 + N_G1 + N_T1)

__global__ void conv_all(const float* __restrict__ in,
                         const float* __restrict__ eW1, const float* __restrict__ eW2,
                         const float* __restrict__ gW1, const float* __restrict__ tW1) {
    long i = (long)blockIdx.x * blockDim.x + threadIdx.x;
    if (i < N_IN) {
        ((uint2*)s_in)[i] = pack_h4(((const float4*)in)[i]);
        return;
    }
    i -= N_IN;
    if (i < N_GIN) {
        int d4 = (int)(i % (Dn / 4));
        long bt = i / (Dn / 4);
        int t  = (int)(bt % Tn);
        long b = bt / Tn;
        const float4* base = (const float4*)(in + b * Gn * Dn);
        float4 a = base[(long)(t + 1) * (Dn / 4) + d4];
        float4 s = base[d4];
        ((uint2*)s_gin)[i] = pack_h4(make_float4(a.x + s.x, a.y + s.y, a.z + s.z, a.w + s.w));
        return;
    }
    i -= N_GIN;
    if (i < N_E1) { ((uint2*)s_we1)[i] = pack_h4(((const float4*)eW1)[i]); return; }
    i -= N_E1;
    if (i < N_E2) { ((uint2*)s_we2)[i] = pack_h4(((const float4*)eW2)[i]); return; }
    i -= N_E2;
    if (i < N_G1) { ((uint2*)s_wg1)[i] = pack_h4(((const float4*)gW1)[i]); return; }
    i -= N_G1;
    if (i < N_T1) { ((uint2*)s_wt1)[i] = pack_h4(((const float4*)tW1)[i]); }
}

// ===========================================================================
// Shared GEMM body (proven R12 mainloop): fp16 A,B; register double-buffer;
// block tile 128x128x32; 256 threads (2M x 4N warps), warp tile 64x32.
// ===========================================================================
#define APITCH 40
#define BPITCH 136
#define A_OFF  0
#define B_OFF (128 * APITCH)
#define BUF_ELEMS (128 * APITCH + 32 * BPITCH)       // 9472
#define TC_SMEM (2 * BUF_ELEMS * 2)                  // 37888 bytes

__device__ __forceinline__ void mma_f16(float* c, const unsigned* a, const unsigned* b) {
    asm volatile(
        "mma.sync.aligned.m16n8k16.row.col.f32.f16.f16.f32 "
        "{%0,%1,%2,%3},{%4,%5,%6,%7},{%8,%9},{%0,%1,%2,%3};"
        : "+f"(c[0]), "+f"(c[1]), "+f"(c[2]), "+f"(c[3])
        : "r"(a[0]), "r"(a[1]), "r"(a[2]), "r"(a[3]), "r"(b[0]), "r"(b[1]));
}
__device__ __forceinline__ void ldsm4(unsigned& r0, unsigned& r1,
                                      unsigned& r2, unsigned& r3, unsigned addr) {
    asm volatile("ldmatrix.sync.aligned.m8n8.x4.shared.b16 {%0,%1,%2,%3},[%4];"
                 : "=r"(r0), "=r"(r1), "=r"(r2), "=r"(r3) : "r"(addr));
}
__device__ __forceinline__ void ldsm4t(unsigned& r0, unsigned& r1,
                                       unsigned& r2, unsigned& r3, unsigned addr) {
    asm volatile("ldmatrix.sync.aligned.m8n8.x4.trans.shared.b16 {%0,%1,%2,%3},[%4];"
                 : "=r"(r0), "=r"(r1), "=r"(r2), "=r"(r3) : "r"(addr));
}

__device__ __forceinline__ void gemm_body(
        const __half* __restrict__ A, const __half* __restrict__ Bw,
        const float* __restrict__ bias,
        float* __restrict__ C, __half* __restrict__ Chalf,
        int K, int lda, int ldb, int ldc, int relu, int halfOut)
{
    extern __shared__ __half sm[];
    int tid  = threadIdx.x;
    int lane = tid & 31, warp = tid >> 5;
    int row0 = blockIdx.x * 128, col0 = blockIdx.y * 128;
    int wm = (warp >> 2) * 64, wn = (warp & 3) * 32;
    int g = lane >> 2, qt = lane & 3;

    unsigned sbase = (unsigned)__cvta_generic_to_shared(sm);

    int rA = (lane & 7) + ((lane >> 3) & 1) * 8;
    int cA = ((lane >> 4) & 1) * 8;
    int rB = (lane & 7) + ((lane >> 3) & 1) * 8;
    int cB = ((lane >> 4) & 1) * 8;

    int aRow = tid >> 2;
    int aK8  = (tid & 3) * 8;
    int bK   = tid >> 3;
    int bN16 = (tid & 7) * 16;

    float acc[4][4][4];
    #pragma unroll
    for (int i = 0; i < 4; i++)
        #pragma unroll
        for (int j = 0; j < 4; j++)
            #pragma unroll
            for (int k = 0; k < 4; k++) acc[i][j][k] = 0.0f;

    const __half* aSrc0 = A + (long)(row0 + aRow) * lda + aK8;
    const __half* aSrc1 = A + (long)(row0 + aRow + 64) * lda + aK8;
    const __half* bSrc  = Bw + (long)bK * ldb + col0 + bN16;

    uint4 va0, va1, vb0, vb1;
    int nIter = K / 32;

    va0 = *(const uint4*)(aSrc0);
    va1 = *(const uint4*)(aSrc1);
    vb0 = *(const uint4*)(bSrc);
    vb1 = *(const uint4*)(bSrc + 8);

    {
        __half* bp = sm;
        *(uint4*)(bp + A_OFF + aRow * APITCH + aK8)        = va0;
        *(uint4*)(bp + A_OFF + (aRow + 64) * APITCH + aK8) = va1;
        *(uint4*)(bp + B_OFF + bK * BPITCH + bN16)     = vb0;
        *(uint4*)(bp + B_OFF + bK * BPITCH + bN16 + 8) = vb1;
    }
    __syncthreads();

    int buf = 0;
    for (int it = 0; it < nIter; it++) {
        if (it + 1 < nIter) {
            int k0 = (it + 1) * 32;
            va0 = *(const uint4*)(aSrc0 + k0);
            va1 = *(const uint4*)(aSrc1 + k0);
            vb0 = *(const uint4*)(bSrc + (long)k0 * ldb);
            vb1 = *(const uint4*)(bSrc + (long)k0 * ldb + 8);
        }

        unsigned bufb = sbase + buf * (BUF_ELEMS * 2);

        #pragma unroll
        for (int ks = 0; ks < 32; ks += 16) {
            unsigned Af[4][4], Bf[4][2];
            #pragma unroll
            for (int mt = 0; mt < 4; mt++) {
                unsigned ad = bufb + (A_OFF + (wm + mt * 16 + rA) * APITCH + ks + cA) * 2;
                ldsm4(Af[mt][0], Af[mt][1], Af[mt][2], Af[mt][3], ad);
            }
            #pragma unroll
            for (int np = 0; np < 2; np++) {
                unsigned bd = bufb + (B_OFF + (ks + rB) * BPITCH + wn + np * 16 + cB) * 2;
                ldsm4t(Bf[2*np][0], Bf[2*np][1], Bf[2*np+1][0], Bf[2*np+1][1], bd);
            }
            #pragma unroll
            for (int mt = 0; mt < 4; mt++)
                #pragma unroll
                for (int nt = 0; nt < 4; nt++)
                    mma_f16(acc[mt][nt], Af[mt], Bf[nt]);
        }

        if (it + 1 < nIter) {
            __half* bp = sm + (buf ^ 1) * BUF_ELEMS;
            *(uint4*)(bp + A_OFF + aRow * APITCH + aK8)        = va0;
            *(uint4*)(bp + A_OFF + (aRow + 64) * APITCH + aK8) = va1;
            *(uint4*)(bp + B_OFF + bK * BPITCH + bN16)     = vb0;
            *(uint4*)(bp + B_OFF + bK * BPITCH + bN16 + 8) = vb1;
        }
        __syncthreads();
        buf ^= 1;
    }

    #pragma unroll
    for (int mt = 0; mt < 4; mt++) {
        #pragma unroll
        for (int nt = 0; nt < 4; nt++) {
            int col = col0 + wn + nt * 8 + 2 * qt;
            long r0 = row0 + wm + mt * 16 + g;
            float b0v = bias[col], b1v = bias[col + 1];
            float2 v0 = make_float2(acc[mt][nt][0] + b0v, acc[mt][nt][1] + b1v);
            float2 v1 = make_float2(acc[mt][nt][2] + b0v, acc[mt][nt][3] + b1v);
            if (relu) {
                v0.x = fmaxf(v0.x, 0.f); v0.y = fmaxf(v0.y, 0.f);
                v1.x = fmaxf(v1.x, 0.f); v1.y = fmaxf(v1.y, 0.f);
            }
            if (halfOut) {
                *(unsigned*)(Chalf + r0 * ldc + col) =
                    (unsigned)__half_as_ushort(__float2half_rn(v0.x))
                  | ((unsigned)__half_as_ushort(__float2half_rn(v0.y)) << 16);
                *(unsigned*)(Chalf + (r0 + 8) * ldc + col) =
                    (unsigned)__half_as_ushort(__float2half_rn(v1.x))
                  | ((unsigned)__half_as_ushort(__float2half_rn(v1.y)) << 16);
            } else {
                *(float2*)&C[r0 * ldc + col] = v0;
                *(float2*)&C[(r0 + 8) * ldc + col] = v1;
            }
        }
    }
}

// ---- generic batched GEMM (expert L2, tower1) ----
__global__ void __launch_bounds__(256, 2)
tc_gemm(const __half* __restrict__ A, const __half* __restrict__ Bw,
        const float* __restrict__ bias,
        float* __restrict__ C, __half* __restrict__ Chalf,
        int K, int lda, int ldb, int ldc,
        long aStride, int aDiv, long bStride, long biasStride, long cStride,
        int relu, int halfOut)
{
    int z = blockIdx.z;
    A  += (long)(z / aDiv) * aStride;
    Bw += (long)z * bStride;
    bias += (long)z * biasStride;
    if (halfOut) Chalf += (long)z * cStride;
    else         C     += (long)z * cStride;
    gemm_body(A, Bw, bias, C, Chalf, K, lda, ldb, ldc, relu, halfOut);
}

// ---- merged expert-L1 (z=0..15) + gate-L1 (z=16..18) launch ----
__global__ void __launch_bounds__(256, 2)
tc_gemm_l1g1(const float* __restrict__ eb1, const float* __restrict__ gb1)
{
    int z = blockIdx.z;
    if (z < NEXP) {
        gemm_body(s_in + (long)(z / NEn) * Dn,
                  s_we1 + (long)z * Dn * Hn,
                  eb1 + (long)z * Hn,
                  nullptr, s_h1 + (long)z * Hn,
                  Dn, Gn * Dn, Hn, NEXP * Hn, 1, 1);
    } else {
        if (blockIdx.y >= GHn / 128) return;
        int t = z - NEXP;
        gemm_body(s_gin + (long)t * Dn,
                  s_wg1 + (long)t * Dn * GHn,
                  gb1 + (long)t * GHn,
                  g_gh + (long)t * GHn, nullptr,
                  Dn, Tn * Dn, GHn, Tn * GHn, 1, 0);
    }
}

// ---------------------------------------------------------------------------
// Scalar FFMA SGEMM for tower layer 2 (N=64).
// ---------------------------------------------------------------------------
#define BM 128
#define BN 128
#define BK 8
#define TM 8
#define TN 8

__global__ __launch_bounds__(256)
void sgemm_bias(const float* __restrict__ A, const float* __restrict__ Bw,
                const float* __restrict__ bias, float* __restrict__ C,
                int N, int K, int lda, int ldb, int ldc,
                long aStride, int aDiv, long bStride, long biasStride, long cStride,
                int relu)
{
    int z = blockIdx.z;
    A    += (long)(z / aDiv) * aStride;
    Bw   += (long)z * bStride;
    bias += (long)z * biasStride;
    C    += (long)z * cStride;

    __shared__ float As[BK][BM];
    __shared__ float Bs[BK][BN];

    int tid  = threadIdx.x;
    int row0 = blockIdx.x * BM;
    int col0 = blockIdx.y * BN;
    int tx = tid % 16;
    int ty = tid / 16;

    int aRow = tid >> 1;
    int aCol = (tid & 1) * 4;
    int bRow = tid >> 5;
    int bCol = (tid & 31) * 4;
    bool bOk = (col0 + bCol) < N;

    float acc[TM][TN];
    #pragma unroll
    for (int i = 0; i < TM; i++)
        #pragma unroll
        for (int j = 0; j < TN; j++) acc[i][j] = 0.0f;

    for (int k0 = 0; k0 < K; k0 += BK) {
        float4 av = *(const float4*)&A[(long)(row0 + aRow) * lda + k0 + aCol];
        As[aCol + 0][aRow] = av.x;
        As[aCol + 1][aRow] = av.y;
        As[aCol + 2][aRow] = av.z;
        As[aCol + 3][aRow] = av.w;
        if (bOk) {
            float4 bv = *(const float4*)&Bw[(long)(k0 + bRow) * ldb + col0 + bCol];
            *(float4*)&Bs[bRow][bCol] = bv;
        }
        __syncthreads();

        #pragma unroll
        for (int kk = 0; kk < BK; kk++) {
            float4 a0 = *(const float4*)&As[kk][ty * TM];
            float4 a1 = *(const float4*)&As[kk][ty * TM + 4];
            float4 b0 = *(const float4*)&Bs[kk][tx * TN];
            float4 b1 = *(const float4*)&Bs[kk][tx * TN + 4];
            float ra[TM] = {a0.x, a0.y, a0.z, a0.w, a1.x, a1.y, a1.z, a1.w};
            float rbv[TN] = {b0.x, b0.y, b0.z, b0.w, b1.x, b1.y, b1.z, b1.w};
            #pragma unroll
            for (int i = 0; i < TM; i++)
                #pragma unroll
                for (int j = 0; j < TN; j++)
                    acc[i][j] += ra[i] * rbv[j];
        }
        __syncthreads();
    }

    #pragma unroll
    for (int i = 0; i < TM; i++) {
        long rr = row0 + ty * TM + i;
        #pragma unroll
        for (int j0 = 0; j0 < TN; j0 += 4) {
            int c = col0 + tx * TN + j0;
            if (c < N) {
                float4 v;
                v.x = acc[i][j0 + 0] + bias[c + 0];
                v.y = acc[i][j0 + 1] + bias[c + 1];
                v.z = acc[i][j0 + 2] + bias[c + 2];
                v.w = acc[i][j0 + 3] + bias[c + 3];
                if (relu) {
                    v.x = fmaxf(v.x, 0.f); v.y = fmaxf(v.y, 0.f);
                    v.z = fmaxf(v.z, 0.f); v.w = fmaxf(v.w, 0.f);
                }
                *(float4*)&C[rr * ldc + c] = v;
            }
        }
    }
}

// ---------------------------------------------------------------------------
// gate2 + softmax, vectorized float4 weight loads (W2 [GH][16] contiguous in k)
// ---------------------------------------------------------------------------
__global__ void gate2_softmax_kernel(const float* __restrict__ W2,
                                     const float* __restrict__ b2) {
    int t = blockIdx.y;
    __shared__ float sW[GHn * NEXP];   // 16 KB, k-contiguous
    __shared__ float sb[NEXP];
    for (int i = threadIdx.x; i < GHn * NEXP; i += blockDim.x)
        sW[i] = W2[(size_t)t * GHn * NEXP + i];
    if (threadIdx.x < NEXP) sb[threadIdx.x] = b2[t * NEXP + threadIdx.x];
    __syncthreads();

    int b = blockIdx.x * blockDim.x + threadIdx.x;
    if (b >= Bn) return;

    const float4* gr = (const float4*)(g_gh + ((size_t)b * Tn + t) * GHn);
    float acc[NEXP];
    #pragma unroll
    for (int k = 0; k < NEXP; k++) acc[k] = sb[k];

    #pragma unroll 4
    for (int h4 = 0; h4 < GHn / 4; h4++) {
        float4 xv = gr[h4];
        float xs[4] = {xv.x, xv.y, xv.z, xv.w};
        #pragma unroll
        for (int e = 0; e < 4; e++) {
            const float4* w4 = (const float4*)(sW + (h4 * 4 + e) * NEXP);
            #pragma unroll
            for (int j = 0; j < 4; j++) {
                float4 wv = w4[j];
                acc[j*4+0] += xs[e] * wv.x;
                acc[j*4+1] += xs[e] * wv.y;
                acc[j*4+2] += xs[e] * wv.z;
                acc[j*4+3] += xs[e] * wv.w;
            }
        }
    }
    float mx = acc[0];
    #pragma unroll
    for (int k = 1; k < NEXP; k++) mx = fmaxf(mx, acc[k]);
    float sum = 0.f;
    #pragma unroll
    for (int k = 0; k < NEXP; k++) { acc[k] = expf(acc[k] - mx); sum += acc[k]; }
    float inv = 1.0f / sum;
    float* o = g_gw + ((size_t)b * Tn + t) * NEXP;
    #pragma unroll
    for (int k = 0; k < NEXP; k++) o[k] = acc[k] * inv;
}

// ---------------------------------------------------------------------------
// agg (fp16 in/out): aggh[b,t,:] = sum_k gw[b,t,k] * embh[b,k,:]
// ---------------------------------------------------------------------------
__global__ void agg_kernel() {
    int b = blockIdx.x;
    int e = threadIdx.x;
    __shared__ float sgw[Tn * NEXP];
    if (threadIdx.x < Tn * NEXP)
        sgw[threadIdx.x] = g_gw[(size_t)b * Tn * NEXP + threadIdx.x];
    __syncthreads();
    const __half* eb = s_embh + (size_t)b * NEXP * En + e;
    float a0 = 0.f, a1 = 0.f, a2 = 0.f;
    #pragma unroll
    for (int k = 0; k < NEXP; k++) {
        float v = __half2float(eb[(size_t)k * En]);
        a0 += sgw[k] * v;
        a1 += sgw[NEXP + k] * v;
        a2 += sgw[2 * NEXP + k] * v;
    }
    __half* o = s_aggh + (size_t)b * Tn * En + e;
    o[0]      = __float2half_rn(a0);
    o[En]     = __float2half_rn(a1);
    o[2 * En] = __float2half_rn(a2);
}

// ---------------------------------------------------------------------------
extern "C" void kernel_launch(void* const* d_in, const int* in_sizes, int n_in,
                              void* d_out, int out_size) {
    const float* inputs = (const float*)d_in[0];
    const float* eW1 = (const float*)d_in[1];
    const float* eb1 = (const float*)d_in[2];
    const float* eW2 = (const float*)d_in[3];
    const float* eb2 = (const float*)d_in[4];
    const float* gW1 = (const float*)d_in[5];
    const float* gb1 = (const float*)d_in[6];
    const float* gW2 = (const float*)d_in[7];
    const float* gb2 = (const float*)d_in[8];
    const float* tW1 = (const float*)d_in[9];
    const float* tb1 = (const float*)d_in[10];
    const float* tW2 = (const float*)d_in[11];
    const float* tb2 = (const float*)d_in[12];
    float* out = (float*)d_out;

    __half *p_h1, *p_embh, *p_we2, *p_wt1, *p_aggh;
    float *p_th;
    cudaGetSymbolAddress((void**)&p_h1,   s_h1);
    cudaGetSymbolAddress((void**)&p_embh, s_embh);
    cudaGetSymbolAddress((void**)&p_we2,  s_we2);
    cudaGetSymbolAddress((void**)&p_wt1,  s_wt1);
    cudaGetSymbolAddress((void**)&p_aggh, s_aggh);
    cudaGetSymbolAddress((void**)&p_th,   g_th);

    cudaFuncSetAttribute(tc_gemm, cudaFuncAttributeMaxDynamicSharedMemorySize, TC_SMEM);
    cudaFuncSetAttribute(tc_gemm_l1g1, cudaFuncAttributeMaxDynamicSharedMemorySize, TC_SMEM);

    // ---- one fused conversion launch ----
    conv_all<<<(unsigned)(N_ALL / 256), 256>>>(inputs, eW1, eW2, gW1, tW1);

    // ---- merged expert L1 + gate L1 ----
    tc_gemm_l1g1<<<dim3(Bn / 128, Hn / 128, NEXP + Tn), 256, TC_SMEM>>>(eb1, gb1);

    // ---- expert layer 2: embh(fp16) = h1 @ eW2 + b2 ----
    tc_gemm<<<dim3(Bn / 128, En / 128, NEXP), 256, TC_SMEM>>>(
        p_h1, p_we2, eb2,
        nullptr, p_embh,
        Hn, NEXP * Hn, En, NEXP * En,
        (long)Hn, 1, (long)Hn * En, (long)En, (long)En, 0, 1);

    gate2_softmax_kernel<<<dim3(Bn / 256, Tn), 256>>>(gW2, gb2);

    agg_kernel<<<Bn, En>>>();

    // ---- tower layer 1 (tensor cores): th(fp32) = relu(aggh @ tW1 + b1) ----
    tc_gemm<<<dim3(Bn / 128, THn / 128, Tn), 256, TC_SMEM>>>(
        p_aggh, p_wt1, tb1,
        p_th, nullptr,
        En, Tn * En, THn, Tn * THn,
        (long)En, 1, (long)En * THn, (long)THn, (long)THn, 1, 0);

    // ---- tower layer 2 -> final output [B, T*TO] ----
    sgemm_bias<<<dim3(Bn / BM, 1, Tn), 256>>>(
        p_th, tW2, tb2, out,
        TOn, THn, Tn * THn, TOn, Tn * TOn,
        (long)THn, 1, (long)THn * TOn, (long)TOn, (long)TOn, 0);
}